// round 1
// baseline (speedup 1.0000x reference)
#include <cuda_runtime.h>

#define KCLS 256
#define WARPS_PER_BLOCK 8
#define THREADS (WARPS_PER_BLOCK * 32)

__global__ __launch_bounds__(THREADS)
void dbf_kernel(const int* __restrict__ data,
                const float* __restrict__ t,
                const float4* __restrict__ noise,
                float4* __restrict__ out,
                int nrows)
{
    __shared__ float sg[KCLS];
    __shared__ float sh[KCLS];

    const int tid = threadIdx.x;

    // Closed-form Cholesky of C0 = (K+0.001) I - 11^T  (equicorrelated):
    //   T_k = a/(k-a), g_k = sqrt(a + T_k), h_k = T_k/g_k, a = K + 0.001
    // Column k of L0 is (0,...,0, g_k, h_k, h_k, ..., h_k)^T.
    {
        const float ALPHA = 256.001f;   // matches float32 C0 the reference builds
        float kf = (float)tid;
        float T  = ALPHA / (kf - ALPHA);           // negative
        float gs = ALPHA + T;                      // positive
        float g  = sqrtf(gs);
        sg[tid] = g;
        sh[tid] = T / g;
    }
    __syncthreads();

    const int warp = tid >> 5;
    const int lane = tid & 31;
    const int row  = blockIdx.x * WARPS_PER_BLOCK + warp;
    if (row >= nrows) return;

    // Per-row scalars
    const float tv = __ldg(t + row);
    const int   x  = __ldg(data + row);
    float sb = fminf(tv, 1.0f - 1e-6f);            // clip upper
    const bool lo = (sb < 1e-10f);
    sb = fmaxf(sb, 1e-10f);
    const float beta = sb * sb;

    // Load 8 contiguous noise values per lane (coalesced float4 x2)
    const float4* nrow = noise + (long long)row * (KCLS / 4);
    float4 n0 = __ldg(nrow + lane * 2 + 0);
    float4 n1 = __ldg(nrow + lane * 2 + 1);
    float v[8] = {n0.x, n0.y, n0.z, n0.w, n1.x, n1.y, n1.z, n1.w};

    const int kbase = lane * 8;
    float g[8], h[8];
    #pragma unroll
    for (int i = 0; i < 8; i++) {
        g[i] = sg[kbase + i];
        h[i] = sh[kbase + i];
    }

    // y_j = g_j v_j + sum_{k<j} h_k v_k  ->  exclusive prefix scan of h*v
    float p[8];
    float run = 0.0f;
    #pragma unroll
    for (int i = 0; i < 8; i++) {
        p[i] = run;
        run = fmaf(h[i], v[i], run);
    }
    // warp inclusive scan of per-lane totals
    float inc = run;
    #pragma unroll
    for (int d = 1; d < 32; d <<= 1) {
        float nb = __shfl_up_sync(0xFFFFFFFFu, inc, d);
        if (lane >= d) inc += nb;
    }
    // exclusive: shift down by one lane
    float excl = __shfl_up_sync(0xFFFFFFFFu, inc, 1);
    if (lane == 0) excl = 0.0f;

    // logits_k = beta*(K*[k==x] - 1) + sb*y_k
    float lg[8];
    float mx = -3.4e38f;
    const float on  = 255.0f * beta;   // (K-1)*beta at k==x (  -beta + K*beta )
    const float off = -beta;
    #pragma unroll
    for (int i = 0; i < 8; i++) {
        float y = fmaf(g[i], v[i], excl + p[i]);
        float l = fmaf(sb, y, (kbase + i == x) ? on : off);
        lg[i] = l;
        mx = fmaxf(mx, l);
    }
    // warp max
    #pragma unroll
    for (int d = 16; d >= 1; d >>= 1)
        mx = fmaxf(mx, __shfl_xor_sync(0xFFFFFFFFu, mx, d));

    // exp + sum
    float e[8];
    float s = 0.0f;
    #pragma unroll
    for (int i = 0; i < 8; i++) {
        e[i] = __expf(lg[i] - mx);
        s += e[i];
    }
    #pragma unroll
    for (int d = 16; d >= 1; d >>= 1)
        s += __shfl_xor_sync(0xFFFFFFFFu, s, d);

    const float r = __fdividef(1.0f, s);
    const float uni = 1.0f / 256.0f;

    float o[8];
    #pragma unroll
    for (int i = 0; i < 8; i++)
        o[i] = lo ? uni : e[i] * r;

    float4* orow = out + (long long)row * (KCLS / 4);
    float4 w0 = make_float4(o[0], o[1], o[2], o[3]);
    float4 w1 = make_float4(o[4], o[5], o[6], o[7]);
    orow[lane * 2 + 0] = w0;
    orow[lane * 2 + 1] = w1;
}

extern "C" void kernel_launch(void* const* d_in, const int* in_sizes, int n_in,
                              void* d_out, int out_size)
{
    const int*    data  = (const int*)d_in[0];
    const float*  t     = (const float*)d_in[1];
    const float4* noise = (const float4*)d_in[2];
    float4*       out   = (float4*)d_out;

    const int nrows = in_sizes[0];                 // B*S = 16384
    const int blocks = (nrows + WARPS_PER_BLOCK - 1) / WARPS_PER_BLOCK;
    dbf_kernel<<<blocks, THREADS>>>(data, t, noise, out, nrows);
}